// round 12
// baseline (speedup 1.0000x reference)
#include <cuda_runtime.h>

// N-body all-pairs gravity, fp32. fma-pipe-rate bound (22.6 cyc/warp-interaction
// = 12 fma-class ops x rt2 measured across R3/R4/R6). This round moves the
// m*d^-1.5 computation off the fma pipe:  w = ex2(-1.5*lg2(d2) + lg2(m)),
// with lg2(m) precomputed at tile load. 3 FMUL -> 1 FFMA-imm(rt1) + 1 extra MUFU.
// fma-pipe cost/interaction: 24 -> 19 cyc. MUFU: 8 -> 16 cyc (still under).

constexpr int NBODY   = 8192;
constexpr int BLOCK   = 256;
constexpr int IBLK    = 4;
constexpr int ISTRIDE = NBODY / IBLK;         // 2048
constexpr int NSPLIT  = 128;                  // j-dimension splits
constexpr int CHUNK   = NBODY / NSPLIT;       // 64 j-bodies per tile (1 KB)

__device__ __forceinline__ float lg2_approx(float x) {
    float r; asm("lg2.approx.f32 %0, %1;" : "=f"(r) : "f"(x)); return r;
}
__device__ __forceinline__ float ex2_approx(float x) {
    float r; asm("ex2.approx.f32 %0, %1;" : "=f"(r) : "f"(x)); return r;
}

__global__ __launch_bounds__(BLOCK)
void nbody_kernel(const float* __restrict__ pos,
                  const float* __restrict__ mass,
                  float* __restrict__ out)
{
    __shared__ float4 sh[CHUNK];   // (x, y, z, lg2(m))

    const int i0    = blockIdx.x * BLOCK + threadIdx.x;   // [0, 2048)
    const int jBase = blockIdx.y * CHUNK;

    if (threadIdx.x < CHUNK) {
        const int j = jBase + threadIdx.x;
        sh[threadIdx.x] = make_float4(pos[3 * j + 0], pos[3 * j + 1],
                                      pos[3 * j + 2], lg2_approx(mass[j]));
    }
    __syncthreads();

    float px[IBLK], py[IBLK], pz[IBLK];
    float fx[IBLK], fy[IBLK], fz[IBLK];
#pragma unroll
    for (int k = 0; k < IBLK; ++k) {
        const int i = i0 + k * ISTRIDE;
        px[k] = pos[3 * i + 0];
        py[k] = pos[3 * i + 1];
        pz[k] = pos[3 * i + 2];
        fx[k] = 0.f; fy[k] = 0.f; fz[k] = 0.f;
    }

#pragma unroll 8
    for (int t = 0; t < CHUNK; ++t) {
        const float4 b = sh[t];          // one LDS.128 serves 4 i-bodies
#pragma unroll
        for (int k = 0; k < IBLK; ++k) { // 4 independent chains
            const float dx = b.x - px[k];
            const float dy = b.y - py[k];
            const float dz = b.z - pz[k];
            const float d2 = fmaf(dx, dx, fmaf(dy, dy, fmaf(dz, dz, 1e-4f)));
            // w = m * d2^-1.5 = ex2(-1.5*lg2(d2) + lg2(m))
            const float L = lg2_approx(d2);              // MUFU.LG2
            const float e = fmaf(-1.5f, L, b.w);         // FFMA-imm (rt 1)
            const float w = ex2_approx(e);               // MUFU.EX2
            fx[k] = fmaf(w, dx, fx[k]);
            fy[k] = fmaf(w, dy, fy[k]);
            fz[k] = fmaf(w, dz, fz[k]);
        }
    }

#pragma unroll
    for (int k = 0; k < IBLK; ++k) {
        const int i = i0 + k * ISTRIDE;
        atomicAdd(&out[3 * i + 0], fx[k]);
        atomicAdd(&out[3 * i + 1], fy[k]);
        atomicAdd(&out[3 * i + 2], fz[k]);
    }
}

extern "C" void kernel_launch(void* const* d_in, const int* in_sizes, int n_in,
                              void* d_out, int out_size)
{
    const float* pos  = (const float*)d_in[0];   // [8192, 3] fp32
    const float* mass = (const float*)d_in[1];   // [8192]    fp32
    float*       out  = (float*)d_out;           // [8192, 3] fp32

    cudaMemsetAsync(out, 0, (size_t)out_size * sizeof(float));

    dim3 grid(ISTRIDE / BLOCK, NSPLIT);          // 8 x 128 = 1024 CTAs
    nbody_kernel<<<grid, BLOCK>>>(pos, mass, out);
}